// round 1
// baseline (speedup 1.0000x reference)
#include <cuda_runtime.h>
#include <cuda_bf16.h>
#include <math.h>

// Problem constants
#define Bq   8
#define Lq   1024
#define Dq   1024
#define Nq   32
#define Mq   (Bq * Lq)          // 8192 rows

// ---------------- scratch (device globals; no allocations allowed) ----------
__device__ float g_xin[(size_t)Mq * Dq];        // in_proj output (B*L, D)
__device__ float g_y  [(size_t)Mq * Dq];        // post-SSM, skip+gelu (B*L, D)
__device__ float g_z  [(size_t)Mq * 2 * Dq];    // GLU pre-activation (B*L, 2D)
__device__ float g_yg [(size_t)Mq * Dq];        // GLU output (B*L, D)
__device__ float g_wre[Dq * Nq];
__device__ float g_wim[Dq * Nq];
__device__ float g_cre[Dq * Nq];                // 2*Re(Ceff)
__device__ float g_cim[Dq * Nq];                // 2*Im(Ceff)

// ---------------- precompute w = exp(dt*A), Ceff = C*(w-1)/A ----------------
__global__ void precompute_kernel(const float* __restrict__ log_dt,
                                  const float* __restrict__ Cc,
                                  const float* __restrict__ log_A_real,
                                  const float* __restrict__ A_imag) {
    int idx = blockIdx.x * blockDim.x + threadIdx.x;
    if (idx >= Dq * Nq) return;
    int d = idx / Nq;
    float dt   = expf(log_dt[d]);
    float a_re = -expf(log_A_real[idx]);
    float a_im = A_imag[idx];
    float x_re = a_re * dt;
    float x_im = a_im * dt;
    float e    = expf(x_re);
    float w_re = e * cosf(x_im);
    float w_im = e * sinf(x_im);
    // (w-1)/A
    float n_re = w_re - 1.0f, n_im = w_im;
    float den  = a_re * a_re + a_im * a_im;
    float f_re = (n_re * a_re + n_im * a_im) / den;
    float f_im = (n_im * a_re - n_re * a_im) / den;
    float c_re = Cc[idx * 2 + 0];
    float c_im = Cc[idx * 2 + 1];
    g_wre[idx] = w_re;
    g_wim[idx] = w_im;
    g_cre[idx] = 2.0f * (c_re * f_re - c_im * f_im);
    g_cim[idx] = 2.0f * (c_re * f_im + c_im * f_re);
}

// ---------------- SGEMM: C = A(MxK) * W(NxK)^T + bias (+ residual) ----------
// 128x128 block tile, BK=8, 256 threads, 8x8 micro tile, double-buffered smem.
template <int EPI>   // 0: +bias   1: +bias +residual
__global__ void __launch_bounds__(256)
sgemm_kernel(const float* __restrict__ A, const float* __restrict__ W,
             const float* __restrict__ bias, const float* __restrict__ R,
             float* __restrict__ C, int M, int Nn, int K) {
    __shared__ float As[2][8][128];
    __shared__ float Bs[2][8][128];

    const int bx = blockIdx.x;   // N tile
    const int by = blockIdx.y;   // M tile
    const int tid = threadIdx.x;
    const int tx = tid & 15;
    const int ty = tid >> 4;

    const float* Ab = A + (size_t)(by * 128) * K;
    const float* Wb = W + (size_t)(bx * 128) * K;

    const int lrow = tid >> 1;          // 0..127
    const int lcol = (tid & 1) * 4;     // 0 or 4

    // prefetch tile 0
    float4 av = *(const float4*)(Ab + (size_t)lrow * K + lcol);
    float4 bv = *(const float4*)(Wb + (size_t)lrow * K + lcol);
    As[0][lcol + 0][lrow] = av.x; As[0][lcol + 1][lrow] = av.y;
    As[0][lcol + 2][lrow] = av.z; As[0][lcol + 3][lrow] = av.w;
    Bs[0][lcol + 0][lrow] = bv.x; Bs[0][lcol + 1][lrow] = bv.y;
    Bs[0][lcol + 2][lrow] = bv.z; Bs[0][lcol + 3][lrow] = bv.w;
    __syncthreads();

    float acc[8][8];
#pragma unroll
    for (int i = 0; i < 8; ++i)
#pragma unroll
        for (int j = 0; j < 8; ++j) acc[i][j] = 0.0f;

    const int nk = K / 8;
    for (int kt = 0; kt < nk; ++kt) {
        const int cur = kt & 1, nxt = cur ^ 1;
        if (kt + 1 < nk) {
            av = *(const float4*)(Ab + (size_t)lrow * K + (kt + 1) * 8 + lcol);
            bv = *(const float4*)(Wb + (size_t)lrow * K + (kt + 1) * 8 + lcol);
        }
#pragma unroll
        for (int k = 0; k < 8; ++k) {
            float4 a0 = *(const float4*)&As[cur][k][ty * 4];
            float4 a1 = *(const float4*)&As[cur][k][ty * 4 + 64];
            float4 b0 = *(const float4*)&Bs[cur][k][tx * 4];
            float4 b1 = *(const float4*)&Bs[cur][k][tx * 4 + 64];
            float ar[8] = {a0.x, a0.y, a0.z, a0.w, a1.x, a1.y, a1.z, a1.w};
            float br[8] = {b0.x, b0.y, b0.z, b0.w, b1.x, b1.y, b1.z, b1.w};
#pragma unroll
            for (int i = 0; i < 8; ++i)
#pragma unroll
                for (int j = 0; j < 8; ++j)
                    acc[i][j] = fmaf(ar[i], br[j], acc[i][j]);
        }
        if (kt + 1 < nk) {
            As[nxt][lcol + 0][lrow] = av.x; As[nxt][lcol + 1][lrow] = av.y;
            As[nxt][lcol + 2][lrow] = av.z; As[nxt][lcol + 3][lrow] = av.w;
            Bs[nxt][lcol + 0][lrow] = bv.x; Bs[nxt][lcol + 1][lrow] = bv.y;
            Bs[nxt][lcol + 2][lrow] = bv.z; Bs[nxt][lcol + 3][lrow] = bv.w;
        }
        __syncthreads();
    }

    // epilogue
#pragma unroll
    for (int ih = 0; ih < 2; ++ih) {
#pragma unroll
        for (int i = 0; i < 4; ++i) {
            int row = by * 128 + ih * 64 + ty * 4 + i;
#pragma unroll
            for (int jh = 0; jh < 2; ++jh) {
                int col = bx * 128 + jh * 64 + tx * 4;
                float4 bsv = *(const float4*)&bias[col];
                float4 v;
                v.x = acc[ih * 4 + i][jh * 4 + 0] + bsv.x;
                v.y = acc[ih * 4 + i][jh * 4 + 1] + bsv.y;
                v.z = acc[ih * 4 + i][jh * 4 + 2] + bsv.z;
                v.w = acc[ih * 4 + i][jh * 4 + 3] + bsv.w;
                if (EPI == 1) {
                    float4 rv = *(const float4*)&R[(size_t)row * Nn + col];
                    v.x += rv.x; v.y += rv.y; v.z += rv.z; v.w += rv.w;
                }
                *(float4*)&C[(size_t)row * Nn + col] = v;
            }
        }
    }
}

// ---------------- diagonal-SSM scan + skip + GELU ----------------------------
// grid: (D/32, B). block: 1024 threads = 32 warps. warp w -> channel d0+w,
// lane n -> complex mode. Reads x_in (B*L, D), writes y (B*L, D).
__global__ void __launch_bounds__(1024)
scan_kernel(const float* __restrict__ xin, const float* __restrict__ dskip,
            float* __restrict__ y) {
    const int warp = threadIdx.x >> 5;
    const int lane = threadIdx.x & 31;
    const int dtile = blockIdx.x;            // 0..31
    const int b = blockIdx.y;                // 0..7
    const int d = dtile * 32 + warp;

    const float w_re = g_wre[d * Nq + lane];
    const float w_im = g_wim[d * Nq + lane];
    const float c_re = g_cre[d * Nq + lane];
    const float c_im = g_cim[d * Nq + lane];
    const float skip = dskip[d];

    __shared__ float ut[32][33];
    __shared__ float yt[32][33];

    const float* xbase = xin + (size_t)b * Lq * Dq + dtile * 32;
    float*       ybase = y   + (size_t)b * Lq * Dq + dtile * 32;

    float sre = 0.0f, sim = 0.0f;

    for (int t = 0; t < Lq / 32; ++t) {
        // cooperative coalesced load of a 32(l) x 32(d) tile
        ut[warp][lane] = xbase[(size_t)(t * 32 + warp) * Dq + lane];
        __syncthreads();

#pragma unroll
        for (int j = 0; j < 32; ++j) {
            float u = ut[j][warp];                 // broadcast
            float nre = fmaf(w_re, sre, u);
            nre = fmaf(-w_im, sim, nre);
            float nim = w_re * sim;
            nim = fmaf(w_im, sre, nim);
            sre = nre; sim = nim;
            float val = fmaf(c_re, sre, -c_im * sim);  // Re(2*Ceff*s)
#pragma unroll
            for (int off = 16; off; off >>= 1)
                val += __shfl_xor_sync(0xffffffffu, val, off);
            if (lane == 0) yt[j][warp] = fmaf(u, skip, val);
        }
        __syncthreads();

        // writeout with exact GELU, coalesced
        float v = yt[warp][lane];
        float g = 0.5f * v * (1.0f + erff(v * 0.70710678118654752f));
        ybase[(size_t)(t * 32 + warp) * Dq + lane] = g;
        __syncthreads();
    }
}

// ---------------- GLU elementwise: yg = a * sigmoid(g) ----------------------
__global__ void glu_kernel(const float* __restrict__ z, float* __restrict__ yg) {
    int i = blockIdx.x * blockDim.x + threadIdx.x;   // over M*D/4
    if (i >= Mq * Dq / 4) return;
    int row = i / (Dq / 4);
    int c4  = i % (Dq / 4);
    const float4* za = (const float4*)(z + (size_t)row * 2 * Dq);
    const float4* zg = (const float4*)(z + (size_t)row * 2 * Dq + Dq);
    float4 a = za[c4];
    float4 g = zg[c4];
    float4 o;
    o.x = a.x / (1.0f + expf(-g.x));
    o.y = a.y / (1.0f + expf(-g.y));
    o.z = a.z / (1.0f + expf(-g.z));
    o.w = a.w / (1.0f + expf(-g.w));
    ((float4*)(yg + (size_t)row * Dq))[c4] = o;
}

// ---------------- launch --------------------------------------------------
extern "C" void kernel_launch(void* const* d_in, const int* in_sizes, int n_in,
                              void* d_out, int out_size) {
    const float* x          = (const float*)d_in[0];
    const float* in_W       = (const float*)d_in[1];
    const float* in_b       = (const float*)d_in[2];
    const float* log_dt     = (const float*)d_in[3];
    const float* Cc         = (const float*)d_in[4];
    const float* log_A_real = (const float*)d_in[5];
    const float* A_imag     = (const float*)d_in[6];
    const float* D_skip     = (const float*)d_in[7];
    const float* glu_W      = (const float*)d_in[8];
    const float* glu_b      = (const float*)d_in[9];
    const float* out_W      = (const float*)d_in[10];
    const float* out_b      = (const float*)d_in[11];
    float* out = (float*)d_out;

    float *xin, *yv, *zv, *yg;
    cudaGetSymbolAddress((void**)&xin, g_xin);
    cudaGetSymbolAddress((void**)&yv,  g_y);
    cudaGetSymbolAddress((void**)&zv,  g_z);
    cudaGetSymbolAddress((void**)&yg,  g_yg);

    // 1) SSM parameter precompute
    precompute_kernel<<<(Dq * Nq + 255) / 256, 256>>>(log_dt, Cc, log_A_real, A_imag);

    // 2) in_proj: x_in = x @ in_W^T + in_b
    {
        dim3 grid(Dq / 128, Mq / 128);
        sgemm_kernel<0><<<grid, 256>>>(x, in_W, in_b, nullptr, xin, Mq, Dq, Dq);
    }

    // 3) SSM scan + skip + GELU
    {
        dim3 grid(Dq / 32, Bq);
        scan_kernel<<<grid, 1024>>>(xin, D_skip, yv);
    }

    // 4) GLU pre-activation: z = y @ glu_W^T + glu_b  (N = 2D)
    {
        dim3 grid(2 * Dq / 128, Mq / 128);
        sgemm_kernel<0><<<grid, 256>>>(yv, glu_W, glu_b, nullptr, zv, Mq, 2 * Dq, Dq);
    }

    // 5) GLU: yg = a * sigmoid(g)
    glu_kernel<<<(Mq * Dq / 4 + 255) / 256, 256>>>(zv, yg);

    // 6) out_proj + residual: out = yg @ out_W^T + out_b + x
    {
        dim3 grid(Dq / 128, Mq / 128);
        sgemm_kernel<1><<<grid, 256>>>(yg, out_W, out_b, x, out, Mq, Dq, Dq);
    }
}